// round 7
// baseline (speedup 1.0000x reference)
#include <cuda_runtime.h>

#define NC 4
#define CS 512
#define NS 256
#define HD 512
#define H  256
#define GAMMA_C 12.0f

#define TI 16          // i-rows per CTA
#define JB 32          // j-cols per CTA (= warp width)
#define KC 32          // k per stage (16 k-pairs)
#define NP 16          // k-pairs per stage

// Scratch: rotated heads
__device__ float g_real[NC * CS * H];
__device__ float g_imag[NC * CS * H];

// ---------------- Kernel A: rotate heads by relation phase ----------------
__global__ void rotate_kernel(const float* __restrict__ heads,
                              const float* __restrict__ rel) {
    int i = blockIdx.x;      // 0..2047
    int k = threadIdx.x;     // 0..255
    float re = heads[i * HD + k];
    float im = heads[i * HD + H + k];
    float ph = rel[i * H + k] * 62.8318530717958648f;   // rel * (pi/0.05)
    float s, c;
    __sincosf(ph, &s, &c);
    g_real[i * H + k] = re * c - im * s;
    g_imag[i * H + k] = re * s + im * c;
}

// ---------------- f32x2 helpers ----------------
__device__ __forceinline__ unsigned long long addx2(unsigned long long a, unsigned long long b) {
    unsigned long long d;
    asm("add.rn.f32x2 %0, %1, %2;" : "=l"(d) : "l"(a), "l"(b));
    return d;
}
__device__ __forceinline__ unsigned long long mulx2(unsigned long long a, unsigned long long b) {
    unsigned long long d;
    asm("mul.rn.f32x2 %0, %1, %2;" : "=l"(d) : "l"(a), "l"(b));
    return d;
}
__device__ __forceinline__ unsigned long long fmax2(unsigned long long a, unsigned long long b, unsigned long long c) {
    unsigned long long d;
    asm("fma.rn.f32x2 %0, %1, %2, %3;" : "=l"(d) : "l"(a), "l"(b), "l"(c));
    return d;
}
__device__ __forceinline__ float sqrt_fast(float x) {
    float y;
    asm("sqrt.approx.f32 %0, %1;" : "=f"(y) : "f"(x));
    return y;
}
__device__ __forceinline__ unsigned long long lds64(const float2* p) {
    return *reinterpret_cast<const unsigned long long*>(p);
}

// complex |h - t| for a packed k-pair; tails pre-negated so sub becomes add
__device__ __forceinline__ void accum_pair(unsigned long long hr, unsigned long long hm,
                                           unsigned long long tr, unsigned long long ti,
                                           float& a0, float& a1) {
    unsigned long long dr = addx2(hr, tr);
    unsigned long long di = addx2(hm, ti);
    unsigned long long s2 = mulx2(dr, dr);
    s2 = fmax2(di, di, s2);
    float lo, hi;
    asm("mov.b64 {%0, %1}, %2;" : "=f"(lo), "=f"(hi) : "l"(s2));
    a0 += sqrt_fast(lo);
    a1 += sqrt_fast(hi);
}

// ---------------- Kernel B: lanes = j, broadcast heads ----------------
__global__ __launch_bounds__(256, 7) void score_kernel(const float* __restrict__ tails,
                                                       float* __restrict__ out) {
    __shared__ float2 s_tr[NP][JB];   // negated tail real, [k-pair][j]
    __shared__ float2 s_ti[NP][JB];   // negated tail imag
    __shared__ float2 s_hr[TI][NP];   // head real,  [i-row][k-pair]
    __shared__ float2 s_hi[TI][NP];   // head imag

    const int tid  = threadIdx.x;
    const int lane = tid & 31;        // j within block
    const int w    = tid >> 5;        // warp 0..7

    const int c  = blockIdx.z;
    const int bi = blockIdx.x;        // 0..31
    const int bj = blockIdx.y;        // 0..7

    const int gi0 = c * CS + bi * TI;
    const float* tb = tails + (size_t)(c * NS + bj * JB) * HD;

    const int r0 = 2 * w;             // this warp's two i-rows
    const int r1 = 2 * w + 1;

    float a0l = 0.f, a0h = 0.f;       // row r0
    float a1l = 0.f, a1h = 0.f;       // row r1

    for (int k0 = 0; k0 < H; k0 += KC) {
        __syncthreads();
        // stage tails (negated): thread -> (p = w, w+8 ; j = lane)
        #pragma unroll
        for (int s = 0; s < 2; s++) {
            int p = w + 8 * s;        // 0..15
            float2 v = *reinterpret_cast<const float2*>(&tb[(size_t)lane * HD + k0 + 2 * p]);
            s_tr[p][lane] = make_float2(-v.x, -v.y);
            float2 u = *reinterpret_cast<const float2*>(&tb[(size_t)lane * HD + H + k0 + 2 * p]);
            s_ti[p][lane] = make_float2(-u.x, -u.y);
        }
        // stage heads: thread -> (i = tid>>4, p = tid&15); coalesced 128B per row
        {
            int i = tid >> 4;         // 0..15
            int p = tid & 15;         // 0..15
            s_hr[i][p] = *reinterpret_cast<const float2*>(&g_real[(size_t)(gi0 + i) * H + k0 + 2 * p]);
            s_hi[i][p] = *reinterpret_cast<const float2*>(&g_imag[(size_t)(gi0 + i) * H + k0 + 2 * p]);
        }
        __syncthreads();

        #pragma unroll
        for (int p = 0; p < NP; p++) {
            unsigned long long tr = lds64(&s_tr[p][lane]);   // per-lane, conflict-free
            unsigned long long ti = lds64(&s_ti[p][lane]);
            {   // row r0 — uniform-address broadcast loads
                unsigned long long hr = lds64(&s_hr[r0][p]);
                unsigned long long hm = lds64(&s_hi[r0][p]);
                accum_pair(hr, hm, tr, ti, a0l, a0h);
            }
            {   // row r1
                unsigned long long hr = lds64(&s_hr[r1][p]);
                unsigned long long hm = lds64(&s_hi[r1][p]);
                accum_pair(hr, hm, tr, ti, a1l, a1h);
            }
        }
    }

    const int gj = bj * JB + lane;
    out[((size_t)c * CS + bi * TI + r0) * NS + gj] = GAMMA_C - (a0l + a0h);
    out[((size_t)c * CS + bi * TI + r1) * NS + gj] = GAMMA_C - (a1l + a1h);
}

extern "C" void kernel_launch(void* const* d_in, const int* in_sizes, int n_in,
                              void* d_out, int out_size) {
    const float* heads = (const float*)d_in[0];
    const float* rel   = (const float*)d_in[1];
    const float* tails = (const float*)d_in[2];
    float* out = (float*)d_out;

    rotate_kernel<<<NC * CS, H>>>(heads, rel);
    dim3 grid(CS / TI, NS / JB, NC);   // (32, 8, 4) = 1024 CTAs, single wave at 7 CTAs/SM
    score_kernel<<<grid, 256>>>(tails, out);
}

// round 8
// speedup vs baseline: 1.2805x; 1.2805x over previous
#include <cuda_runtime.h>

#define NC 4
#define CS 512
#define NS 256
#define HD 512
#define H  256
#define GAMMA_C 12.0f

// Tile config (R6-proven layout): CTA = 32 i x 16 j, 256 threads, 2i x 1j per thread
#define TI 32
#define TJ 16
#define TK 32
#define TKP 36         // 144B row stride: 16B-aligned rows, 4-bank shift -> conflict-free LDS.128

// Scratch: rotated heads
__device__ float g_real[NC * CS * H];
__device__ float g_imag[NC * CS * H];

// ---------------- Kernel A: rotate heads by relation phase ----------------
__global__ void rotate_kernel(const float* __restrict__ heads,
                              const float* __restrict__ rel) {
    int i = blockIdx.x;      // 0..2047
    int k = threadIdx.x;     // 0..255
    float re = heads[i * HD + k];
    float im = heads[i * HD + H + k];
    float ph = rel[i * H + k] * 62.8318530717958648f;   // rel * (pi/0.05)
    float s, c;
    __sincosf(ph, &s, &c);
    g_real[i * H + k] = re * c - im * s;
    g_imag[i * H + k] = re * s + im * c;
}

// ---------------- f32x2 helpers ----------------
__device__ __forceinline__ unsigned long long addx2(unsigned long long a, unsigned long long b) {
    unsigned long long d;
    asm("add.rn.f32x2 %0, %1, %2;" : "=l"(d) : "l"(a), "l"(b));
    return d;
}
__device__ __forceinline__ unsigned long long mulx2(unsigned long long a, unsigned long long b) {
    unsigned long long d;
    asm("mul.rn.f32x2 %0, %1, %2;" : "=l"(d) : "l"(a), "l"(b));
    return d;
}
__device__ __forceinline__ unsigned long long fmax2(unsigned long long a, unsigned long long b, unsigned long long c) {
    unsigned long long d;
    asm("fma.rn.f32x2 %0, %1, %2, %3;" : "=l"(d) : "l"(a), "l"(b), "l"(c));
    return d;
}
__device__ __forceinline__ float sqrt_fast(float x) {
    float y;
    asm("sqrt.approx.f32 %0, %1;" : "=f"(y) : "f"(x));
    return y;
}
__device__ __forceinline__ ulonglong2 lds128(const float* p) {
    return *reinterpret_cast<const ulonglong2*>(p);
}

// complex |h - t| for a packed k-pair; tails pre-negated so sub becomes add
__device__ __forceinline__ void accum_pair(unsigned long long hr, unsigned long long hm,
                                           unsigned long long tr, unsigned long long ti,
                                           float& a0, float& a1) {
    unsigned long long dr = addx2(hr, tr);
    unsigned long long di = addx2(hm, ti);
    unsigned long long s2 = mulx2(dr, dr);
    s2 = fmax2(di, di, s2);
    float lo, hi;
    asm("mov.b64 {%0, %1}, %2;" : "=f"(lo), "=f"(hi) : "l"(s2));
    a0 += sqrt_fast(lo);
    a1 += sqrt_fast(hi);
}

// ---------------- Kernel B: tiled score, LDS.128 inner loop ----------------
__global__ __launch_bounds__(256, 7) void score_kernel(const float* __restrict__ tails,
                                                       float* __restrict__ out) {
    __shared__ __align__(16) float s_re[TI][TKP];
    __shared__ __align__(16) float s_im[TI][TKP];
    __shared__ __align__(16) float s_tr[TJ][TKP];   // negated tail real
    __shared__ __align__(16) float s_ti[TJ][TKP];   // negated tail imag

    const int tid = threadIdx.x;
    const int c   = blockIdx.z;
    const int bi  = blockIdx.x;       // 0..15
    const int bj  = blockIdx.y;       // 0..15

    const int tjx = tid & 15;         // j within tile
    const int tix = tid >> 4;         // i within tile: rows tix and tix+16

    const int gi0 = c * CS + bi * TI;
    const float* tbase = tails + (size_t)(c * NS + bj * TJ) * HD;

    float accA0 = 0.f, accA1 = 0.f;
    float accB0 = 0.f, accB1 = 0.f;

    for (int k0 = 0; k0 < H; k0 += TK) {
        __syncthreads();
        // stage real/imag: 32 rows x 32 k = 256 float4 each; 1 per thread per array
        {
            int r  = tid >> 3;               // 0..31
            int c4 = (tid & 7) * 4;          // 0..28
            float4 v = *reinterpret_cast<const float4*>(&g_real[(size_t)(gi0 + r) * H + k0 + c4]);
            *reinterpret_cast<float4*>(&s_re[r][c4]) = v;
            float4 w = *reinterpret_cast<const float4*>(&g_imag[(size_t)(gi0 + r) * H + k0 + c4]);
            *reinterpret_cast<float4*>(&s_im[r][c4]) = w;
        }
        // stage tails (negated): 16 rows x 32 k = 128 float4 per array; half threads each
        {
            int r  = tid >> 3;               // 0..31
            int c4 = (tid & 7) * 4;          // 0..28
            if (r < TJ) {
                float4 v = *reinterpret_cast<const float4*>(&tbase[(size_t)r * HD + k0 + c4]);
                *reinterpret_cast<float4*>(&s_tr[r][c4]) = make_float4(-v.x, -v.y, -v.z, -v.w);
            } else {
                int rr = r - TJ;
                float4 w = *reinterpret_cast<const float4*>(&tbase[(size_t)rr * HD + H + k0 + c4]);
                *reinterpret_cast<float4*>(&s_ti[rr][c4]) = make_float4(-w.x, -w.y, -w.z, -w.w);
            }
        }
        __syncthreads();

        #pragma unroll
        for (int kk = 0; kk < TK; kk += 4) {
            ulonglong2 tr = lds128(&s_tr[tjx][kk]);
            ulonglong2 ti = lds128(&s_ti[tjx][kk]);
            {   // rows tix
                ulonglong2 hr = lds128(&s_re[tix][kk]);
                ulonglong2 hm = lds128(&s_im[tix][kk]);
                accum_pair(hr.x, hm.x, tr.x, ti.x, accA0, accA1);
                accum_pair(hr.y, hm.y, tr.y, ti.y, accA0, accA1);
            }
            {   // rows tix+16
                ulonglong2 hr = lds128(&s_re[tix + 16][kk]);
                ulonglong2 hm = lds128(&s_im[tix + 16][kk]);
                accum_pair(hr.x, hm.x, tr.x, ti.x, accB0, accB1);
                accum_pair(hr.y, hm.y, tr.y, ti.y, accB0, accB1);
            }
        }
    }

    const int gj = bj * TJ + tjx;
    const int gi = bi * TI + tix;
    out[((size_t)c * CS + gi)      * NS + gj] = GAMMA_C - (accA0 + accA1);
    out[((size_t)c * CS + gi + 16) * NS + gj] = GAMMA_C - (accB0 + accB1);
}

extern "C" void kernel_launch(void* const* d_in, const int* in_sizes, int n_in,
                              void* d_out, int out_size) {
    const float* heads = (const float*)d_in[0];
    const float* rel   = (const float*)d_in[1];
    const float* tails = (const float*)d_in[2];
    float* out = (float*)d_out;

    rotate_kernel<<<NC * CS, H>>>(heads, rel);
    dim3 grid(CS / TI, NS / TJ, NC);   // (16, 16, 4) = 1024 CTAs, single wave at 7 CTAs/SM
    score_kernel<<<grid, 256>>>(tails, out);
}

// round 9
// speedup vs baseline: 1.6143x; 1.2607x over previous
#include <cuda_runtime.h>

#define NC 4
#define CS 512
#define NS 256
#define HD 512
#define H  256
#define GAMMA_C 12.0f

#define TIB 16         // i-rows per CTA (2 per warp, 8 warps)
#define TJB 16         // j-rows per CTA (tails staged in smem)

// Scratch: rotated heads
__device__ float g_real[NC * CS * H];
__device__ float g_imag[NC * CS * H];

// ---------------- Kernel A: rotate heads by relation phase ----------------
__global__ void rotate_kernel(const float* __restrict__ heads,
                              const float* __restrict__ rel) {
    int i = blockIdx.x;      // 0..2047
    int k = threadIdx.x;     // 0..255
    float re = heads[i * HD + k];
    float im = heads[i * HD + H + k];
    float ph = rel[i * H + k] * 62.8318530717958648f;   // rel * (pi/0.05)
    float s, c;
    __sincosf(ph, &s, &c);
    g_real[i * H + k] = re * c - im * s;
    g_imag[i * H + k] = re * s + im * c;
}

// ---------------- f32x2 helpers ----------------
__device__ __forceinline__ unsigned long long addx2(unsigned long long a, unsigned long long b) {
    unsigned long long d;
    asm("add.rn.f32x2 %0, %1, %2;" : "=l"(d) : "l"(a), "l"(b));
    return d;
}
__device__ __forceinline__ unsigned long long mulx2(unsigned long long a, unsigned long long b) {
    unsigned long long d;
    asm("mul.rn.f32x2 %0, %1, %2;" : "=l"(d) : "l"(a), "l"(b));
    return d;
}
__device__ __forceinline__ unsigned long long fmax2(unsigned long long a, unsigned long long b, unsigned long long c) {
    unsigned long long d;
    asm("fma.rn.f32x2 %0, %1, %2, %3;" : "=l"(d) : "l"(a), "l"(b), "l"(c));
    return d;
}
__device__ __forceinline__ float sqrt_fast(float x) {
    float y;
    asm("sqrt.approx.f32 %0, %1;" : "=f"(y) : "f"(x));
    return y;
}

// |h - t| for packed k-pair; tails pre-negated
__device__ __forceinline__ void accum_pair(unsigned long long hr, unsigned long long hm,
                                           unsigned long long tr, unsigned long long ti,
                                           float& acc) {
    unsigned long long dr = addx2(hr, tr);
    unsigned long long di = addx2(hm, ti);
    unsigned long long s2 = mulx2(dr, dr);
    s2 = fmax2(di, di, s2);
    float lo, hi;
    asm("mov.b64 {%0, %1}, %2;" : "=f"(lo), "=f"(hi) : "l"(s2));
    acc += sqrt_fast(lo);
    acc += sqrt_fast(hi);
}

__device__ __forceinline__ float warp_sum(float v) {
    #pragma unroll
    for (int o = 16; o >= 1; o >>= 1)
        v += __shfl_xor_sync(0xFFFFFFFFu, v, o);
    return v;
}

// ---------------- Kernel B: lanes span k; heads in registers ----------------
__global__ __launch_bounds__(256, 4) void score_kernel(const float* __restrict__ tails,
                                                       float* __restrict__ out) {
    // tails tile: 16 j-rows x 512 floats (re 0..255, im 256..511), negated
    __shared__ float ts[TJB * HD];

    const int tid  = threadIdx.x;
    const int lane = tid & 31;
    const int w    = tid >> 5;        // warp 0..7

    const int c  = blockIdx.z;
    const int bi = blockIdx.x;        // 0..31  (512/16)
    const int bj = blockIdx.y;        // 0..15  (256/16)

    // ---- stage tails once (negated): linear copy of 2048 float4 ----
    {
        const float4* src = reinterpret_cast<const float4*>(tails + (size_t)(c * NS + bj * TJB) * HD);
        float4* dst = reinterpret_cast<float4*>(ts);
        #pragma unroll
        for (int it = 0; it < 8; it++) {
            float4 v = src[tid + it * 256];
            dst[tid + it * 256] = make_float4(-v.x, -v.y, -v.z, -v.w);
        }
    }

    // ---- load this warp's two head rows into registers ----
    const int i0 = c * CS + bi * TIB + 2 * w;     // global row
    unsigned long long hr0[4], hi0[4], hr1[4], hi1[4];
    {
        const unsigned long long* r0r = reinterpret_cast<const unsigned long long*>(&g_real[(size_t)i0 * H]);
        const unsigned long long* r0i = reinterpret_cast<const unsigned long long*>(&g_imag[(size_t)i0 * H]);
        const unsigned long long* r1r = reinterpret_cast<const unsigned long long*>(&g_real[(size_t)(i0 + 1) * H]);
        const unsigned long long* r1i = reinterpret_cast<const unsigned long long*>(&g_imag[(size_t)(i0 + 1) * H]);
        #pragma unroll
        for (int m = 0; m < 4; m++) {
            int off = lane + 32 * m;              // ull index: k-pair (2*lane + 64*m)
            hr0[m] = r0r[off];
            hi0[m] = r0i[off];
            hr1[m] = r1r[off];
            hi1[m] = r1i[off];
        }
    }

    __syncthreads();

    const int gj0 = bj * TJB;
    float* orow0 = out + ((size_t)(i0)     ) * NS + gj0;
    float* orow1 = out + ((size_t)(i0 + 1) ) * NS + gj0;

    for (int j = 0; j < TJB; j++) {
        const unsigned long long* tr = reinterpret_cast<const unsigned long long*>(&ts[j * HD]);
        const unsigned long long* ti = reinterpret_cast<const unsigned long long*>(&ts[j * HD + H]);

        float a0 = 0.f, a1 = 0.f;
        #pragma unroll
        for (int m = 0; m < 4; m++) {
            int off = lane + 32 * m;
            unsigned long long t_r = tr[off];     // conflict-free: 16-lane phases cover banks once
            unsigned long long t_i = ti[off];
            accum_pair(hr0[m], hi0[m], t_r, t_i, a0);
            accum_pair(hr1[m], hi1[m], t_r, t_i, a1);
        }
        a0 = warp_sum(a0);
        a1 = warp_sum(a1);
        if (lane == 0) orow0[j] = GAMMA_C - a0;
        if (lane == 1) orow1[j] = GAMMA_C - a1;   // a1 valid on all lanes post-butterfly
    }
}

extern "C" void kernel_launch(void* const* d_in, const int* in_sizes, int n_in,
                              void* d_out, int out_size) {
    const float* heads = (const float*)d_in[0];
    const float* rel   = (const float*)d_in[1];
    const float* tails = (const float*)d_in[2];
    float* out = (float*)d_out;

    rotate_kernel<<<NC * CS, H>>>(heads, rel);
    dim3 grid(CS / TIB, NS / TJB, NC);   // (32, 16, 4) = 2048 CTAs
    score_kernel<<<grid, 256>>>(tails, out);
}

// round 10
// speedup vs baseline: 1.9058x; 1.1806x over previous
#include <cuda_runtime.h>

#define NC 4
#define CS 512
#define NS 256
#define HD 512
#define H  256
#define GAMMA_C 12.0f

#define TIB 16         // i-rows per CTA (2 per warp, 8 warps)
#define TJB 8          // j-rows per CTA (tails staged in smem)

// Scratch: rotated heads
__device__ float g_real[NC * CS * H];
__device__ float g_imag[NC * CS * H];

// ---------------- Kernel A: rotate heads by relation phase ----------------
__global__ void rotate_kernel(const float* __restrict__ heads,
                              const float* __restrict__ rel) {
    int i = blockIdx.x;      // 0..2047
    int k = threadIdx.x;     // 0..255
    float re = heads[i * HD + k];
    float im = heads[i * HD + H + k];
    float ph = rel[i * H + k] * 62.8318530717958648f;   // rel * (pi/0.05)
    float s, c;
    __sincosf(ph, &s, &c);
    g_real[i * H + k] = re * c - im * s;
    g_imag[i * H + k] = re * s + im * c;
}

// ---------------- f32x2 helpers ----------------
__device__ __forceinline__ unsigned long long addx2(unsigned long long a, unsigned long long b) {
    unsigned long long d;
    asm("add.rn.f32x2 %0, %1, %2;" : "=l"(d) : "l"(a), "l"(b));
    return d;
}
__device__ __forceinline__ unsigned long long mulx2(unsigned long long a, unsigned long long b) {
    unsigned long long d;
    asm("mul.rn.f32x2 %0, %1, %2;" : "=l"(d) : "l"(a), "l"(b));
    return d;
}
__device__ __forceinline__ unsigned long long fmax2(unsigned long long a, unsigned long long b, unsigned long long c) {
    unsigned long long d;
    asm("fma.rn.f32x2 %0, %1, %2, %3;" : "=l"(d) : "l"(a), "l"(b), "l"(c));
    return d;
}
__device__ __forceinline__ float sqrt_fast(float x) {
    float y;
    asm("sqrt.approx.f32 %0, %1;" : "=f"(y) : "f"(x));
    return y;
}

// |h - t| for packed k-pair; tails pre-negated
__device__ __forceinline__ void accum_pair(unsigned long long hr, unsigned long long hm,
                                           unsigned long long tr, unsigned long long ti,
                                           float& acc) {
    unsigned long long dr = addx2(hr, tr);
    unsigned long long di = addx2(hm, ti);
    unsigned long long s2 = mulx2(dr, dr);
    s2 = fmax2(di, di, s2);
    float lo, hi;
    asm("mov.b64 {%0, %1}, %2;" : "=f"(lo), "=f"(hi) : "l"(s2));
    acc += sqrt_fast(lo);
    acc += sqrt_fast(hi);
}

// ---------------- Kernel B: lanes span k; heads in registers ----------------
__global__ __launch_bounds__(256, 4) void score_kernel(const float* __restrict__ tails,
                                                       float* __restrict__ out) {
    // tails tile: TJB j-rows x 512 floats (re 0..255, im 256..511), negated
    __shared__ float ts[TJB * HD];

    const int tid  = threadIdx.x;
    const int lane = tid & 31;
    const int w    = tid >> 5;        // warp 0..7

    const int c  = blockIdx.z;
    const int bi = blockIdx.x;        // 0..31  (512/16)
    const int bj = blockIdx.y;        // 0..31  (256/8)

    // ---- stage tails once (negated): linear copy of TJB*HD/4 float4 ----
    {
        const float4* src = reinterpret_cast<const float4*>(tails + (size_t)(c * NS + bj * TJB) * HD);
        float4* dst = reinterpret_cast<float4*>(ts);
        #pragma unroll
        for (int it = 0; it < (TJB * HD / 4) / 256; it++) {
            float4 v = src[tid + it * 256];
            dst[tid + it * 256] = make_float4(-v.x, -v.y, -v.z, -v.w);
        }
    }

    // ---- load this warp's two head rows into registers ----
    const int i0 = c * CS + bi * TIB + 2 * w;     // global row
    unsigned long long hr0[4], hi0[4], hr1[4], hi1[4];
    {
        const unsigned long long* r0r = reinterpret_cast<const unsigned long long*>(&g_real[(size_t)i0 * H]);
        const unsigned long long* r0i = reinterpret_cast<const unsigned long long*>(&g_imag[(size_t)i0 * H]);
        const unsigned long long* r1r = reinterpret_cast<const unsigned long long*>(&g_real[(size_t)(i0 + 1) * H]);
        const unsigned long long* r1i = reinterpret_cast<const unsigned long long*>(&g_imag[(size_t)(i0 + 1) * H]);
        #pragma unroll
        for (int m = 0; m < 4; m++) {
            int off = lane + 32 * m;              // ull index: k-pair (2*lane + 64*m)
            hr0[m] = r0r[off];
            hi0[m] = r0i[off];
            hr1[m] = r1r[off];
            hi1[m] = r1i[off];
        }
    }

    __syncthreads();

    const int gj0 = bj * TJB;
    float* orow0 = out + (size_t)(i0)     * NS + gj0;
    float* orow1 = out + (size_t)(i0 + 1) * NS + gj0;

    #pragma unroll 2
    for (int j = 0; j < TJB; j += 2) {
        const unsigned long long* trA = reinterpret_cast<const unsigned long long*>(&ts[j * HD]);
        const unsigned long long* tiA = reinterpret_cast<const unsigned long long*>(&ts[j * HD + H]);
        const unsigned long long* trB = reinterpret_cast<const unsigned long long*>(&ts[(j + 1) * HD]);
        const unsigned long long* tiB = reinterpret_cast<const unsigned long long*>(&ts[(j + 1) * HD + H]);

        float a0 = 0.f, a1 = 0.f;     // j   : rows 0,1
        float b0 = 0.f, b1 = 0.f;     // j+1 : rows 0,1
        #pragma unroll
        for (int m = 0; m < 4; m++) {
            int off = lane + 32 * m;
            unsigned long long tAr = trA[off];
            unsigned long long tAi = tiA[off];
            unsigned long long tBr = trB[off];
            unsigned long long tBi = tiB[off];
            accum_pair(hr0[m], hi0[m], tAr, tAi, a0);
            accum_pair(hr1[m], hi1[m], tAr, tAi, a1);
            accum_pair(hr0[m], hi0[m], tBr, tBi, b0);
            accum_pair(hr1[m], hi1[m], tBr, tBi, b1);
        }

        // ---- merged 4-way butterfly: outputs on lanes 0 (a0), 8 (a1), 16 (b0), 24 (b1)
        a0 += __shfl_xor_sync(0xFFFFFFFFu, a0, 16);
        a1 += __shfl_xor_sync(0xFFFFFFFFu, a1, 16);
        b0 += __shfl_xor_sync(0xFFFFFFFFu, b0, 16);
        b1 += __shfl_xor_sync(0xFFFFFFFFu, b1, 16);
        float m0 = (lane < 16) ? a0 : b0;
        float m1 = (lane < 16) ? a1 : b1;
        m0 += __shfl_xor_sync(0xFFFFFFFFu, m0, 8);
        m1 += __shfl_xor_sync(0xFFFFFFFFu, m1, 8);
        float n = ((lane & 8) == 0) ? m0 : m1;
        n += __shfl_xor_sync(0xFFFFFFFFu, n, 4);
        n += __shfl_xor_sync(0xFFFFFFFFu, n, 2);
        n += __shfl_xor_sync(0xFFFFFFFFu, n, 1);

        if ((lane & 7) == 0) {
            int idx = lane >> 3;                       // 0..3
            float* p = (idx & 1) ? orow1 : orow0;
            p[j + (idx >> 1)] = GAMMA_C - n;
        }
    }
}

extern "C" void kernel_launch(void* const* d_in, const int* in_sizes, int n_in,
                              void* d_out, int out_size) {
    const float* heads = (const float*)d_in[0];
    const float* rel   = (const float*)d_in[1];
    const float* tails = (const float*)d_in[2];
    float* out = (float*)d_out;

    rotate_kernel<<<NC * CS, H>>>(heads, rel);
    dim3 grid(CS / TIB, NS / TJB, NC);   // (32, 32, 4) = 4096 CTAs
    score_kernel<<<grid, 256>>>(tails, out);
}